// round 2
// baseline (speedup 1.0000x reference)
#include <cuda_runtime.h>
#include <math.h>

#define Hh 1024
#define Ww 1024
#define Cc 16
#define HW (1024*1024)

#define ZD (-0.26794919243112270647)   // sqrt(3) - 2

static __device__ float g_tmp[Cc*HW];    // row-filtered image
static __device__ float g_coef[Cc*HW];   // fully prefiltered coefficients
static __device__ float g_dcoef[18];     // prefiltered control-point displacements (2x3x3)
static __device__ float g_zp[34];        // z^i

// --- exact reference 3-point spline_filter1d (horizon = 3), eager-mode fp32 --
// Every reference primitive = one separately-rounded rn op (no contraction),
// except the 3-elem tensordot which is an fma chain (dot codegen).
__device__ __forceinline__ void filt3(float v0, float v1, float v2, float* o) {
    const float Zf    = (float)ZD;
    const float Z2f   = (float)(ZD*ZD);
    const float GAIN  = (float)((1.0-ZD)*(1.0-1.0/ZD));
    const float LASTC = (float)(ZD/(ZD*ZD-1.0));
    float c0 = __fmul_rn(v0, GAIN);
    float c1 = __fmul_rn(v1, GAIN);
    float c2 = __fmul_rn(v2, GAIN);
    // c0' = tensordot(zpow, c[:3]) : acc = fma(z^i, c_i, acc), z^0 = 1
    float cp0 = c0;
    cp0 = __fmaf_rn(Zf,  c1, cp0);
    cp0 = __fmaf_rn(Z2f, c2, cp0);
    // causal scan: out = ci + Z*carry  (mul then add, separate roundings)
    float cp1 = __fadd_rn(c1, __fmul_rn(Zf, cp0));
    float cp2 = __fadd_rn(c2, __fmul_rn(Zf, cp1));
    // last = (Z/(Z^2-1)) * (cp[-1] + Z*cp[-2])
    float last = __fmul_rn(LASTC, __fadd_rn(cp2, __fmul_rn(Zf, cp1)));
    // anticausal: out = Z*(carry - cpi)
    float o1 = __fmul_rn(Zf, __fsub_rn(last, cp1));
    float o0 = __fmul_rn(Zf, __fsub_rn(o1,  cp0));
    o[0] = o0; o[1] = o1; o[2] = last;
}

__global__ void setup_kernel(const float* __restrict__ disp) {
    if (threadIdx.x == 0) {
        double zp = 1.0;
        for (int i = 0; i < 34; i++) { g_zp[i] = (float)zp; zp *= ZD; }
        float d[2][3][3];
        for (int ch = 0; ch < 2; ch++)
            for (int i = 0; i < 3; i++)
                for (int j = 0; j < 3; j++)
                    d[ch][i][j] = __fmul_rn(disp[ch*9 + i*3 + j], 10.0f);   // SIGMA
        // axis 1 (rows index)
        for (int ch = 0; ch < 2; ch++)
            for (int j = 0; j < 3; j++) {
                float o[3];
                filt3(d[ch][0][j], d[ch][1][j], d[ch][2][j], o);
                d[ch][0][j] = o[0]; d[ch][1][j] = o[1]; d[ch][2][j] = o[2];
            }
        // axis 2 (cols index)
        for (int ch = 0; ch < 2; ch++)
            for (int i = 0; i < 3; i++) {
                float o[3];
                filt3(d[ch][i][0], d[ch][i][1], d[ch][i][2], o);
                g_dcoef[ch*9 + i*3 + 0] = o[0];
                g_dcoef[ch*9 + i*3 + 1] = o[1];
                g_dcoef[ch*9 + i*3 + 2] = o[2];
            }
    }
}

// --- row prefilter (along x): warp per row, shuffle scan --------------------
__global__ void __launch_bounds__(256) rowfilt_kernel(const float* __restrict__ img) {
    int warp = blockIdx.x * 8 + (threadIdx.x >> 5);   // 0 .. 16383  (c*1024 + y)
    int lane = threadIdx.x & 31;
    const float* row = img + warp * Ww;
    float* orow = g_tmp + warp * Ww;

    const float z1  = (float)ZD;
    const float z2  = (float)(ZD*ZD);
    const float z4  = (float)(ZD*ZD*ZD*ZD);
    const float z8  = (float)(ZD*ZD*ZD*ZD*ZD*ZD*ZD*ZD);
    const float z16 = z8*z8;
    const float SQ3 = (float)((1.0-ZD)/(1.0+ZD));   // sqrt(3)

    float zl1 = g_zp[lane + 1];    // z^(lane+1)
    float zr  = g_zp[32 - lane];   // z^(32-lane)
    float zl0 = g_zp[lane];        // z^lane

    float xs[32], As[32];
    float carry = 0.0f;

    #pragma unroll
    for (int b = 0; b < 32; b++) {
        float x = row[b*32 + lane];
        xs[b] = x;
        float a = x, v;
        v = __shfl_up_sync(0xffffffffu, a, 1);  if (lane >= 1)  a += z1  * v;
        v = __shfl_up_sync(0xffffffffu, a, 2);  if (lane >= 2)  a += z2  * v;
        v = __shfl_up_sync(0xffffffffu, a, 4);  if (lane >= 4)  a += z4  * v;
        v = __shfl_up_sync(0xffffffffu, a, 8);  if (lane >= 8)  a += z8  * v;
        v = __shfl_up_sync(0xffffffffu, a, 16); if (lane >= 16) a += z16 * v;
        a += zl1 * carry;
        carry = __shfl_sync(0xffffffffu, a, 31);
        As[b] = a;
    }
    float A1022 = __shfl_sync(0xffffffffu, As[31], 30);  // causal state at index 1022

    float carryR = 0.0f;
    #pragma unroll
    for (int b = 31; b >= 0; b--) {
        float x = xs[b];
        float r = x, v;
        v = __shfl_down_sync(0xffffffffu, r, 1);  if (lane < 31) r += z1  * v;
        v = __shfl_down_sync(0xffffffffu, r, 2);  if (lane < 30) r += z2  * v;
        v = __shfl_down_sync(0xffffffffu, r, 4);  if (lane < 28) r += z4  * v;
        v = __shfl_down_sync(0xffffffffu, r, 8);  if (lane < 24) r += z8  * v;
        v = __shfl_down_sync(0xffffffffu, r, 16); if (lane < 16) r += z16 * v;
        r += zr * carryR;
        carryR = __shfl_sync(0xffffffffu, r, 0);
        float d = r - x;          // strict anticausal part
        float t = As[b] + d;
        if (b == 31) t += zr * A1022;                 // right mirror correction
        if (b == 0) {
            float B0 = __shfl_sync(0xffffffffu, d, 0);
            t += zl0 * B0;                            // left mirror correction
        }
        orow[b*32 + lane] = SQ3 * t;
    }
}

// --- column prefilter (along y): register chunks + halo warm-up -------------
__global__ void __launch_bounds__(256) colfilt_kernel() {
    int x  = blockIdx.x * 256 + threadIdx.x;
    int c  = blockIdx.z;
    int ys = blockIdx.y * 32;
    const float* base = g_tmp + c * HW;
    float* ob = g_coef + c * HW;
    const float Zf  = (float)ZD;
    const float SQ3 = (float)((1.0-ZD)/(1.0+ZD));

    float A = 0.0f;
    #pragma unroll
    for (int j = 16; j >= 1; j--) {           // causal warm-up (mirror at top)
        int yy = ys - j; yy = yy < 0 ? -yy : yy;
        A = fmaf(Zf, A, base[yy*Ww + x]);
    }
    float xs[32], As[32];
    #pragma unroll
    for (int j = 0; j < 32; j++) {
        float v = base[(ys + j)*Ww + x];
        A = fmaf(Zf, A, v);
        xs[j] = v; As[j] = A;
    }
    float R = 0.0f;
    #pragma unroll
    for (int j = 15; j >= 0; j--) {           // anticausal warm-up (mirror at bottom)
        int yy = ys + 32 + j; yy = yy > 1023 ? 2046 - yy : yy;
        R = fmaf(Zf, R, base[yy*Ww + x]);
    }
    #pragma unroll
    for (int j = 31; j >= 0; j--) {
        ob[(ys + j)*Ww + x] = SQ3 * fmaf(Zf, R, As[j]);   // sqrt3*(A_j + z*R_{j+1})
        R = fmaf(Zf, R, xs[j]);
    }
}

// --- strict (eager-jax) cubic weights: exact primitive-by-primitive ----------
__device__ __forceinline__ void cubw_strict(float f, float* w) {
    float f2 = __fmul_rn(f, f);
    float f3 = __fmul_rn(f2, f);
    // w0 = ((1 - 3f) + 3f2) - f3, then /6
    float t = __fsub_rn(1.0f, __fmul_rn(3.0f, f));
    t = __fadd_rn(t, __fmul_rn(3.0f, f2));
    t = __fsub_rn(t, f3);
    w[0] = __fdiv_rn(t, 6.0f);
    // w1 = ((4 - 6f2) + 3f3) / 6
    t = __fsub_rn(4.0f, __fmul_rn(6.0f, f2));
    t = __fadd_rn(t, __fmul_rn(3.0f, f3));
    w[1] = __fdiv_rn(t, 6.0f);
    // w2 = (((1 + 3f) + 3f2) - 3f3) / 6
    t = __fadd_rn(1.0f, __fmul_rn(3.0f, f));
    t = __fadd_rn(t, __fmul_rn(3.0f, f2));
    t = __fsub_rn(t, __fmul_rn(3.0f, f3));
    w[2] = __fdiv_rn(t, 6.0f);
    // w3 = f3 / 6
    w[3] = __fdiv_rn(f3, 6.0f);
}

// fast weights for the image gather (loose tolerance path)
__device__ __forceinline__ void cubw_fast(float f, float* w) {
    float f2 = f*f;
    float f3 = f2*f;
    const float S = 1.0f/6.0f;
    w[0] = (1.0f - 3.0f*f + 3.0f*f2 - f3) * S;
    w[1] = (4.0f - 6.0f*f2 + 3.0f*f3) * S;
    w[2] = (1.0f + 3.0f*f + 3.0f*f2 - 3.0f*f3) * S;
    w[3] = f3 * S;
}

__device__ __forceinline__ int mir3(int i) {        // mirror, n=3 (period 4)
    int m = i < 0 ? -i : i;
    m &= 3;
    return m > 2 ? 4 - m : m;
}
__device__ __forceinline__ int refl1024(int i) {    // mirror, n=1024 (small excursions)
    return i < 0 ? -i : (i > 1023 ? 2046 - i : i);
}

// --- main eval: dense field (strict fp32) + cubic image gather + nearest mask
__global__ void __launch_bounds__(256) eval_kernel(const float* __restrict__ mask,
                                                   float* __restrict__ out) {
    int x = blockIdx.x * 256 + threadIdx.x;
    int y = blockIdx.y;
    const float SCL = (float)(2.0/1023.0);

    // ---- dense displacement at (y, x): strict eager-jax fp32 replication ----
    float uy = __fmul_rn((float)y, SCL);
    float ux = __fmul_rn((float)x, SCL);
    float fly = floorf(uy); int iy0 = (int)fly;
    float flx = floorf(ux); int ix0 = (int)flx;
    float fy0 = __fsub_rn(uy, fly);
    float fx0 = __fsub_rn(ux, flx);
    float wy[4], wx[4];
    cubw_strict(fy0, wy); cubw_strict(fx0, wx);
    float dense0 = 0.0f, dense1 = 0.0f;
    #pragma unroll
    for (int a = 0; a < 4; a++) {
        int my = mir3(iy0 + a - 1);
        float r0 = 0.0f, r1 = 0.0f;
        #pragma unroll
        for (int b = 0; b < 4; b++) {
            int mx = mir3(ix0 + b - 1);
            float wb = wx[b];
            r0 = __fadd_rn(r0, __fmul_rn(wb, g_dcoef[my*3 + mx]));
            r1 = __fadd_rn(r1, __fmul_rn(wb, g_dcoef[9 + my*3 + mx]));
        }
        dense0 = __fadd_rn(dense0, __fmul_rn(wy[a], r0));
        dense1 = __fadd_rn(dense1, __fmul_rn(wy[a], r1));
    }
    float sy = __fadd_rn((float)y, dense0);
    float sx = __fadd_rn((float)x, dense1);
    bool valid = (sy >= 0.0f) && (sy <= 1023.0f) && (sx >= 0.0f) && (sx <= 1023.0f);
    int oidx = y*Ww + x;

    if (valid) {
        float fs = floorf(sy); int iy = (int)fs; float fy = sy - fs;
        float gs = floorf(sx); int ix = (int)gs; float fx = sx - gs;
        float Wy[4], Wx[4];
        cubw_fast(fy, Wy); cubw_fast(fx, Wx);
        int ry[4], rx[4];
        #pragma unroll
        for (int a = 0; a < 4; a++) ry[a] = refl1024(iy + a - 1) * Ww;
        #pragma unroll
        for (int b = 0; b < 4; b++) rx[b] = refl1024(ix + b - 1);

        #pragma unroll
        for (int c = 0; c < Cc; c++) {
            const float* p = g_coef + c * HW;
            float s = 0.0f;
            #pragma unroll
            for (int a = 0; a < 4; a++) {
                const float* pr = p + ry[a];
                float row;
                row = Wx[0] * __ldg(pr + rx[0]);
                row = fmaf(Wx[1], __ldg(pr + rx[1]), row);
                row = fmaf(Wx[2], __ldg(pr + rx[2]), row);
                row = fmaf(Wx[3], __ldg(pr + rx[3]), row);
                s = fmaf(Wy[a], row, s);
            }
            out[c*HW + oidx] = s;
        }
        int ny = (int)rintf(sy); ny = ny < 0 ? 0 : (ny > 1023 ? 1023 : ny);  // half-even
        int nx = (int)rintf(sx); nx = nx < 0 ? 0 : (nx > 1023 ? 1023 : nx);
        int midx = ny*Ww + nx;
        #pragma unroll
        for (int c = 0; c < Cc; c++)
            out[Cc*HW + c*HW + oidx] = __ldg(mask + c*HW + midx);
    } else {
        #pragma unroll
        for (int c = 0; c < Cc; c++) {
            out[c*HW + oidx] = 0.0f;
            out[Cc*HW + c*HW + oidx] = 0.0f;
        }
    }
}

extern "C" void kernel_launch(void* const* d_in, const int* in_sizes, int n_in,
                              void* d_out, int out_size) {
    const float* image = (const float*)d_in[0];
    const float* mask  = (const float*)d_in[1];
    const float* disp  = (const float*)d_in[2];
    float* out = (float*)d_out;

    setup_kernel<<<1, 32>>>(disp);
    rowfilt_kernel<<<2048, 256>>>(image);                 // 16384 warps, one per row
    colfilt_kernel<<<dim3(4, 32, 16), 256>>>();
    eval_kernel<<<dim3(4, 1024), 256>>>(mask, out);
}